// round 6
// baseline (speedup 1.0000x reference)
#include <cuda_runtime.h>
#include <cuda_bf16.h>
#include <cuda_fp16.h>

// GCN layer, scatter formulation with fp16 h' storage:
//   1) memset deg=0, memset out=0
//   2) deg histogram over srcs (float RED, 4 edges/thread)
//   3) h' = (features @ K) * rsqrt(max(deg,1))  stored as fp16; norm stored
//   4) edge scatter: out[src] += ew * h'[dst]
//      4 threads/edge (uint4 = 8 halves each), 4 independent edges per thread,
//      all gathers in flight before REDs; 2x red.global.add.v4.f32 per thread.
//   5) out = out * norm[src] + bias  (float4)
//
// Inputs: features f32[100000,32], edge_srcs i32[E], edge_dsts i32[E],
// edge_weights f32[E], kernels f32[32,32], biases f32[32]. Output f32[100000,32].

#define NUM_NODES 100000
#define F 32

__device__ __align__(16) __half g_h[NUM_NODES * F];  // fp16 h' rows (64 B each)
__device__ float g_norm[NUM_NODES];
__device__ float g_deg[NUM_NODES];

// ---------------------------------------------------------------------------
// degree histogram: 4 edges per thread
__global__ __launch_bounds__(512) void deg_kernel(const int* __restrict__ srcs, int E) {
    int t = blockIdx.x * blockDim.x + threadIdx.x;
    int base = t * 4;
#pragma unroll
    for (int k = 0; k < 4; ++k) {
        int e = base + k;
        if (e < E) atomicAdd(&g_deg[srcs[e]], 1.0f);   // no return use -> REDG
    }
}

// transform: one warp per node; lane f computes (features[n] @ K)[:,f] * norm[n]
__global__ void transform_kernel(const float* __restrict__ features,
                                 const float* __restrict__ kernels,
                                 int N) {
    __shared__ float sk[F * F];
    for (int i = threadIdx.x; i < F * F; i += blockDim.x)
        sk[i] = kernels[i];
    __syncthreads();

    int gwarp = (blockIdx.x * blockDim.x + threadIdx.x) >> 5;
    int lane  = threadIdx.x & 31;
    if (gwarp >= N) return;

    float feat = features[gwarp * F + lane];
    float acc = 0.0f;
#pragma unroll
    for (int k = 0; k < F; ++k)
        acc = fmaf(__shfl_sync(0xffffffffu, feat, k), sk[k * F + lane], acc);

    float nrm = rsqrtf(fmaxf(g_deg[gwarp], 1.0f));
    g_h[gwarp * F + lane] = __float2half(acc * nrm);
    if (lane == 0) g_norm[gwarp] = nrm;
}

// edge scatter: 4 threads per edge-slot, 4 edges per thread (e, e+Q, e+2Q, e+3Q).
// Each thread gathers 8 halves (uint4), converts to f32, scales, 2x RED.v4.f32.
__global__ __launch_bounds__(512) void edge_kernel(const int* __restrict__ srcs,
                                                   const int* __restrict__ dsts,
                                                   const float* __restrict__ ew,
                                                   float* __restrict__ out,
                                                   int E, int Q) {
    int t = blockIdx.x * blockDim.x + threadIdx.x;
    int e = t >> 2;        // edge slot
    int c = t & 3;         // 8-feature chunk
    if (e >= Q) return;

    int   se[4], de[4];
    float we[4];
    bool  ok[4];
#pragma unroll
    for (int k = 0; k < 4; ++k) {
        int ee = e + k * Q;
        ok[k] = ee < E;
        if (ok[k]) {
            se[k] = __ldg(srcs + ee);
            de[k] = __ldg(dsts + ee);
            we[k] = __ldg(ew + ee);
        } else {
            se[k] = 0; de[k] = 0; we[k] = 0.0f;
        }
    }

    // gather 8 halves per edge chunk: row = 64 B = 4 uint4
    const uint4* hp = reinterpret_cast<const uint4*>(g_h);
    uint4 raw[4];
#pragma unroll
    for (int k = 0; k < 4; ++k)
        if (ok[k]) raw[k] = __ldg(hp + (size_t)de[k] * 4 + c);

    float* op = out;
#pragma unroll
    for (int k = 0; k < 4; ++k) {
        if (!ok[k]) continue;
        float w = we[k];
        float2 f0 = __half22float2(*reinterpret_cast<__half2*>(&raw[k].x));
        float2 f1 = __half22float2(*reinterpret_cast<__half2*>(&raw[k].y));
        float2 f2 = __half22float2(*reinterpret_cast<__half2*>(&raw[k].z));
        float2 f3 = __half22float2(*reinterpret_cast<__half2*>(&raw[k].w));
        // out row byte offset: features [8c .. 8c+8) -> two 16 B REDs
        float* p = op + (size_t)se[k] * F + c * 8;
        asm volatile(
            "red.global.add.v4.f32 [%0], {%1, %2, %3, %4};"
            :: "l"(p), "f"(f0.x * w), "f"(f0.y * w), "f"(f1.x * w), "f"(f1.y * w)
            : "memory");
        asm volatile(
            "red.global.add.v4.f32 [%0], {%1, %2, %3, %4};"
            :: "l"(p + 4), "f"(f2.x * w), "f"(f2.y * w), "f"(f3.x * w), "f"(f3.y * w)
            : "memory");
    }
}

// finalize: out4 = out4 * norm[n] + bias4  (float4, one chunk per thread)
__global__ __launch_bounds__(512) void finalize_kernel(float* __restrict__ out,
                                                       const float* __restrict__ biases,
                                                       int N) {
    int t = blockIdx.x * blockDim.x + threadIdx.x;
    int n = t >> 3;
    int c = t & 7;
    if (n >= N) return;
    float nrm = g_norm[n];
    float4 b  = reinterpret_cast<const float4*>(biases)[c];
    float4* p = reinterpret_cast<float4*>(out) + (size_t)n * 8 + c;
    float4 v  = *p;
    v.x = fmaf(v.x, nrm, b.x);
    v.y = fmaf(v.y, nrm, b.y);
    v.z = fmaf(v.z, nrm, b.z);
    v.w = fmaf(v.w, nrm, b.w);
    *p = v;
}

extern "C" void kernel_launch(void* const* d_in, const int* in_sizes, int n_in,
                              void* d_out, int out_size) {
    const float* features = (const float*)d_in[0];
    const int*   srcs     = (const int*)d_in[1];
    const int*   dsts     = (const int*)d_in[2];
    const float* ew       = (const float*)d_in[3];
    const float* kernels  = (const float*)d_in[4];
    const float* biases   = (const float*)d_in[5];
    float*       out      = (float*)d_out;

    int N = in_sizes[0] / F;   // 100000
    int E = in_sizes[1];       // 3200000

    // zero accumulators (0 bits == 0.0f)
    cudaMemsetAsync(d_out, 0, (size_t)out_size * sizeof(float));
    {
        void* degp = nullptr;
        cudaGetSymbolAddress(&degp, g_deg);
        cudaMemsetAsync(degp, 0, (size_t)N * sizeof(float));
    }

    {
        int threads = 512;
        int work = (E + 3) / 4;
        deg_kernel<<<(work + threads - 1) / threads, threads>>>(srcs, E);
    }
    {
        int threads = 256;                  // 8 warps = 8 nodes per block
        int blocks = (N + 7) / 8;
        transform_kernel<<<blocks, threads>>>(features, kernels, N);
    }
    {
        int Q = (E + 3) / 4;                // edges per ILP slot
        int threads = 512;
        long long total = (long long)Q * 4; // 4 threads per edge-slot
        int blocks = (int)((total + threads - 1) / threads);
        edge_kernel<<<blocks, threads>>>(srcs, dsts, ew, out, E, Q);
    }
    {
        int threads = 512;
        long long total = (long long)N * 8;
        int blocks = (int)((total + threads - 1) / threads);
        finalize_kernel<<<blocks, threads>>>(out, biases, N);
    }
}

// round 9
// speedup vs baseline: 1.1599x; 1.1599x over previous
#include <cuda_runtime.h>
#include <cuda_bf16.h>

// GCN layer via CSR (no output atomics):
//   1) memset deg=0
//   2) deg histogram over srcs (int RED, 4 edges/thread)
//   3) 3-phase multi-block exclusive scan -> rowptr + cursor
//   4) scatter (ILP-4): pos = atomicAdd(cursor[src]); sorted[pos] = {dst, w}
//   5) transform: h' = (features @ K) * rsqrt(max(deg,1)); store norm
//   6) gather: 8 threads/node, each owns one float4 chunk; loops the node's
//      CSR segment (2-wide unroll), acc += w*h'[dst]; writes acc*norm + bias
//      directly (no memset, no finalize, no atomics).
//
// Inputs: features f32[100000,32], edge_srcs i32[E], edge_dsts i32[E],
// edge_weights f32[E], kernels f32[32,32], biases f32[32]. Output f32[100000,32].

#define NUM_NODES 100000
#define F 32
#define E_MAX 3200000
#define SCAN_BLK 1024
#define NBLK ((NUM_NODES + SCAN_BLK - 1) / SCAN_BLK)   // 98

// Static scratch
__device__ __align__(16) float g_h[NUM_NODES * F];
__device__ float g_norm[NUM_NODES];
__device__ int   g_deg[NUM_NODES];
__device__ int   g_rowptr[NUM_NODES + 1];
__device__ int   g_cursor[NUM_NODES];
__device__ int   g_bsum[NBLK];
__device__ int   g_boff[NBLK];
__device__ __align__(8) int2 g_sorted[E_MAX];          // {dst, __float_as_int(w)}

// ---------------------------------------------------------------------------
// degree histogram: 4 edges/thread, strided for coalescing
__global__ __launch_bounds__(512) void deg_kernel(const int* __restrict__ srcs,
                                                  int E, int Q) {
    int t = blockIdx.x * blockDim.x + threadIdx.x;
    if (t >= Q) return;
#pragma unroll
    for (int k = 0; k < 4; ++k) {
        int e = t + k * Q;
        if (e < E) atomicAdd(&g_deg[srcs[e]], 1);      // no return -> REDG
    }
}

// scan phase A: per-block sums of deg
__global__ __launch_bounds__(SCAN_BLK) void scanA_kernel(int N) {
    __shared__ int ws[32];
    int i = blockIdx.x * SCAN_BLK + threadIdx.x;
    int v = (i < N) ? g_deg[i] : 0;
    int lane = threadIdx.x & 31, wid = threadIdx.x >> 5;
    int s = v;
#pragma unroll
    for (int off = 16; off > 0; off >>= 1)
        s += __shfl_down_sync(0xffffffffu, s, off);
    if (lane == 0) ws[wid] = s;
    __syncthreads();
    if (wid == 0) {
        int x = (lane < SCAN_BLK / 32) ? ws[lane] : 0;
#pragma unroll
        for (int off = 16; off > 0; off >>= 1)
            x += __shfl_down_sync(0xffffffffu, x, off);
        if (lane == 0) g_bsum[blockIdx.x] = x;
    }
}

// scan phase B: single small block scans NBLK block sums -> exclusive offsets
__global__ void scanB_kernel(int N) {
    __shared__ int ws[4];
    int t = threadIdx.x;                 // 128 threads
    int v = (t < NBLK) ? g_bsum[t] : 0;
    int lane = t & 31, wid = t >> 5;
    int iv = v;
#pragma unroll
    for (int off = 1; off < 32; off <<= 1) {
        int o = __shfl_up_sync(0xffffffffu, iv, off);
        if (lane >= off) iv += o;
    }
    if (lane == 31) ws[wid] = iv;
    __syncthreads();
    int add = 0;
    for (int w = 0; w < wid; ++w) add += ws[w];
    iv += add;
    if (t < NBLK) g_boff[t] = iv - v;    // exclusive
    if (t == NBLK - 1) g_rowptr[N] = iv; // total == E
}

// scan phase C: per-block exclusive scan + block offset -> rowptr, cursor
__global__ __launch_bounds__(SCAN_BLK) void scanC_kernel(int N) {
    __shared__ int ws[32];
    int i = blockIdx.x * SCAN_BLK + threadIdx.x;
    int v = (i < N) ? g_deg[i] : 0;
    int lane = threadIdx.x & 31, wid = threadIdx.x >> 5;
    int iv = v;
#pragma unroll
    for (int off = 1; off < 32; off <<= 1) {
        int o = __shfl_up_sync(0xffffffffu, iv, off);
        if (lane >= off) iv += o;
    }
    if (lane == 31) ws[wid] = iv;
    __syncthreads();
    if (wid == 0) {
        int x = (lane < SCAN_BLK / 32) ? ws[lane] : 0;
#pragma unroll
        for (int off = 1; off < 32; off <<= 1) {
            int o = __shfl_up_sync(0xffffffffu, x, off);
            if (lane >= off) x += o;
        }
        ws[lane] = x;
    }
    __syncthreads();
    int excl = iv - v + (wid > 0 ? ws[wid - 1] : 0) + g_boff[blockIdx.x];
    if (i < N) {
        g_rowptr[i] = excl;
        g_cursor[i] = excl;
    }
}

// scatter edges into CSR order, ILP-4 (4 independent atomic chains/thread)
__global__ __launch_bounds__(512) void scatter_kernel(const int* __restrict__ srcs,
                                                      const int* __restrict__ dsts,
                                                      const float* __restrict__ ew,
                                                      int E, int Q) {
    int t = blockIdx.x * blockDim.x + threadIdx.x;
    if (t >= Q) return;
    int  s[4], d[4]; float w[4]; bool ok[4];
#pragma unroll
    for (int k = 0; k < 4; ++k) {
        int e = t + k * Q;
        ok[k] = e < E;
        if (ok[k]) { s[k] = __ldg(srcs + e); d[k] = __ldg(dsts + e); w[k] = __ldg(ew + e); }
    }
    int pos[4];
#pragma unroll
    for (int k = 0; k < 4; ++k)
        if (ok[k]) pos[k] = atomicAdd(&g_cursor[s[k]], 1);
#pragma unroll
    for (int k = 0; k < 4; ++k)
        if (ok[k]) g_sorted[pos[k]] = make_int2(d[k], __float_as_int(w[k]));
}

// transform: one warp per node; lane f computes (features[n] @ K)[:,f] * norm[n]
__global__ void transform_kernel(const float* __restrict__ features,
                                 const float* __restrict__ kernels,
                                 int N) {
    __shared__ float sk[F * F];
    for (int i = threadIdx.x; i < F * F; i += blockDim.x)
        sk[i] = kernels[i];
    __syncthreads();

    int gwarp = (blockIdx.x * blockDim.x + threadIdx.x) >> 5;
    int lane  = threadIdx.x & 31;
    if (gwarp >= N) return;

    float feat = features[gwarp * F + lane];
    float acc = 0.0f;
#pragma unroll
    for (int k = 0; k < F; ++k)
        acc = fmaf(__shfl_sync(0xffffffffu, feat, k), sk[k * F + lane], acc);

    float nrm = rsqrtf(fmaxf((float)g_deg[gwarp], 1.0f));
    g_h[gwarp * F + lane] = acc * nrm;
    if (lane == 0) g_norm[gwarp] = nrm;
}

// gather: 8 threads per node (c = float4 chunk). 2-wide unrolled CSR loop.
// All 8 threads of a node read the same int2 (broadcast); row gathers coalesce.
__global__ __launch_bounds__(256) void gather_kernel(const float* __restrict__ biases,
                                                     float* __restrict__ out, int N) {
    int t = blockIdx.x * blockDim.x + threadIdx.x;
    int node = t >> 3;
    int c    = t & 7;
    if (node >= N) return;

    int i   = g_rowptr[node];
    int end = g_rowptr[node + 1];
    const float4* hp = reinterpret_cast<const float4*>(g_h);

    float4 acc = make_float4(0.f, 0.f, 0.f, 0.f);
    for (; i + 1 < end; i += 2) {
        int2 p0 = __ldg(&g_sorted[i]);
        int2 p1 = __ldg(&g_sorted[i + 1]);
        float  w0 = __int_as_float(p0.y);
        float  w1 = __int_as_float(p1.y);
        float4 v0 = __ldg(hp + (size_t)p0.x * 8 + c);
        float4 v1 = __ldg(hp + (size_t)p1.x * 8 + c);
        acc.x = fmaf(w0, v0.x, acc.x); acc.y = fmaf(w0, v0.y, acc.y);
        acc.z = fmaf(w0, v0.z, acc.z); acc.w = fmaf(w0, v0.w, acc.w);
        acc.x = fmaf(w1, v1.x, acc.x); acc.y = fmaf(w1, v1.y, acc.y);
        acc.z = fmaf(w1, v1.z, acc.z); acc.w = fmaf(w1, v1.w, acc.w);
    }
    if (i < end) {
        int2 p = __ldg(&g_sorted[i]);
        float  w = __int_as_float(p.y);
        float4 v = __ldg(hp + (size_t)p.x * 8 + c);
        acc.x = fmaf(w, v.x, acc.x); acc.y = fmaf(w, v.y, acc.y);
        acc.z = fmaf(w, v.z, acc.z); acc.w = fmaf(w, v.w, acc.w);
    }

    float nrm = g_norm[node];
    float4 b  = reinterpret_cast<const float4*>(biases)[c];
    float4 r;
    r.x = fmaf(acc.x, nrm, b.x);
    r.y = fmaf(acc.y, nrm, b.y);
    r.z = fmaf(acc.z, nrm, b.z);
    r.w = fmaf(acc.w, nrm, b.w);
    reinterpret_cast<float4*>(out)[(size_t)node * 8 + c] = r;
}

extern "C" void kernel_launch(void* const* d_in, const int* in_sizes, int n_in,
                              void* d_out, int out_size) {
    const float* features = (const float*)d_in[0];
    const int*   srcs     = (const int*)d_in[1];
    const int*   dsts     = (const int*)d_in[2];
    const float* ew       = (const float*)d_in[3];
    const float* kernels  = (const float*)d_in[4];
    const float* biases   = (const float*)d_in[5];
    float*       out      = (float*)d_out;

    int N = in_sizes[0] / F;   // 100000
    int E = in_sizes[1];       // 3200000
    int Q = (E + 3) / 4;

    {
        void* degp = nullptr;
        cudaGetSymbolAddress(&degp, g_deg);
        cudaMemsetAsync(degp, 0, (size_t)N * sizeof(int));
    }
    {
        int threads = 512;
        deg_kernel<<<(Q + threads - 1) / threads, threads>>>(srcs, E, Q);
    }
    scanA_kernel<<<NBLK, SCAN_BLK>>>(N);
    scanB_kernel<<<1, 128>>>(N);
    scanC_kernel<<<NBLK, SCAN_BLK>>>(N);
    {
        int threads = 512;
        scatter_kernel<<<(Q + threads - 1) / threads, threads>>>(srcs, dsts, ew, E, Q);
    }
    {
        int threads = 256;              // 8 warps = 8 nodes per block
        int blocks = (N + 7) / 8;
        transform_kernel<<<blocks, threads>>>(features, kernels, N);
    }
    {
        int threads = 256;              // 8 threads per node
        long long total = (long long)N * 8;
        int blocks = (int)((total + threads - 1) / threads);
        gather_kernel<<<blocks, threads>>>(biases, out, N);
    }
}